// round 13
// baseline (speedup 1.0000x reference)
#include <cuda_runtime.h>
#include <cstdint>

// Painting: sequential alpha-composite of N=128 RGBA layers onto a ones canvas.
// canvas = canvas*(1-a) + a*poly, a = poly[alpha]*0.8, per-pixel recurrence.
//
// R13: champion R12 structure (thread-private cp.async pipeline, in-loop
// conditional issue, running byte-pointer addressing, .L2::256B prefetch,
// zero synchronization) with the final single-variable probe: DEPTH 4 -> 3.
// Measured depth curve (4: 88.2% DRAM, 5: 82.8%, 6: 81.4%) is monotone
// worse with depth — L1tex queue-position latency grows with pending
// stages — so the untested shallower point is the remaining candidate.
// 12KB smem, 1024 blocks x 64 thr, each thread owns 4 consecutive pixels.

#define OPACITY 0.8f
#define HW      262144              // 512*512
#define NLAYERS 128
#define DEPTH   3                   // stages (1 layer per stage)
#define TPB     64
#define LAYER_BYTES ((size_t)4 * HW * 4)   // bytes per layer (4 planes)

__device__ __forceinline__ void cp_async16(uint32_t smem_addr, const void* gptr)
{
    asm volatile("cp.async.cg.shared.global.L2::256B [%0], [%1], 16;\n"
                 :: "r"(smem_addr), "l"(gptr));
}
__device__ __forceinline__ void cp_commit()
{
    asm volatile("cp.async.commit_group;\n" ::: "memory");
}
__device__ __forceinline__ void cp_wait_oldest()
{
    asm volatile("cp.async.wait_group %0;\n" :: "n"(DEPTH - 1) : "memory");
}

__global__ __launch_bounds__(TPB)
void painting_kernel(const float* __restrict__ polys,
                     float* __restrict__ out)
{
    // [stage][channel][thread] float4 : 3*4*64*16B = 12KB
    __shared__ float4 sbuf[DEPTH][4][TPB];

    const int t = threadIdx.x;
    const int q = (blockIdx.x * TPB + t) * 4;   // first of this thread's 4 pixels

    const uint32_t smem0 = (uint32_t)__cvta_generic_to_shared(&sbuf[0][0][t]);
    // sbuf[slot][c][t] = smem0 + (slot*4 + c) * (TPB*16)

    // running source pointer: advances by one layer per issue; channels are
    // fixed +c*HW float offsets. Addressing independent of the layer index.
    const char* gptr = (const char*)(polys + q);

    auto issue_layer = [&](int slot) {
#pragma unroll
        for (int c = 0; c < 4; ++c) {
            cp_async16(smem0 + (uint32_t)(slot * 4 + c) * (TPB * 16),
                       gptr + (size_t)c * (HW * 4));
        }
        cp_commit();
        gptr += LAYER_BYTES;
    };

    // ---- prologue: fill the pipe ----
#pragma unroll
    for (int k = 0; k < DEPTH; ++k)
        issue_layer(k);

    float4 c0 = make_float4(1.f, 1.f, 1.f, 1.f);
    float4 c1 = c0, c2 = c0, c3 = c0;

    int slot = 0;
    for (int l = 0; l < NLAYERS; ++l) {
        cp_wait_oldest();   // this thread's oldest stage complete; it reads
                            // only its own cp.async results -> no syncs.

        float4 p0 = sbuf[slot][0][t];
        float4 p1 = sbuf[slot][1][t];
        float4 p2 = sbuf[slot][2][t];
        float4 p3 = sbuf[slot][3][t];

        float ax = p3.x * OPACITY;
        float ay = p3.y * OPACITY;
        float az = p3.z * OPACITY;
        float aw = p3.w * OPACITY;

        c0.x = fmaf(ax, p0.x - c0.x, c0.x);
        c0.y = fmaf(ay, p0.y - c0.y, c0.y);
        c0.z = fmaf(az, p0.z - c0.z, c0.z);
        c0.w = fmaf(aw, p0.w - c0.w, c0.w);

        c1.x = fmaf(ax, p1.x - c1.x, c1.x);
        c1.y = fmaf(ay, p1.y - c1.y, c1.y);
        c1.z = fmaf(az, p1.z - c1.z, c1.z);
        c1.w = fmaf(aw, p1.w - c1.w, c1.w);

        c2.x = fmaf(ax, p2.x - c2.x, c2.x);
        c2.y = fmaf(ay, p2.y - c2.y, c2.y);
        c2.z = fmaf(az, p2.z - c2.z, c2.z);
        c2.w = fmaf(aw, p2.w - c2.w, c2.w);

        c3.x = fmaf(ax, p3.x - c3.x, c3.x);
        c3.y = fmaf(ay, p3.y - c3.y, c3.y);
        c3.z = fmaf(az, p3.z - c3.z, c3.z);
        c3.w = fmaf(aw, p3.w - c3.w, c3.w);

        if (l + DEPTH < NLAYERS)
            issue_layer(slot);
        else
            cp_commit();    // empty group keeps wait_group count aligned

        slot = (slot == DEPTH - 1) ? 0 : slot + 1;
    }

    *(float4*)(out +          q) = c0;
    *(float4*)(out +     HW + q) = c1;
    *(float4*)(out + 2 * HW + q) = c2;
    *(float4*)(out + 3 * HW + q) = c3;
}

extern "C" void kernel_launch(void* const* d_in, const int* in_sizes, int n_in,
                              void* d_out, int out_size)
{
    const float* polys = (const float*)d_in[0];
    float* out = (float*)d_out;

    const int blocks = HW / 4 / TPB;   // 1024
    painting_kernel<<<blocks, TPB>>>(polys, out);
}

// round 14
// speedup vs baseline: 1.0036x; 1.0036x over previous
#include <cuda_runtime.h>
#include <cstdint>

// Painting: sequential alpha-composite of N=128 RGBA layers onto a ones canvas.
// canvas = canvas*(1-a) + a*poly, a = poly[alpha]*0.8, per-pixel recurrence.
//
// R13: champion R12 structure (thread-private cp.async pipeline, in-loop
// conditional issue, running byte-pointer addressing, .L2::256B prefetch,
// zero synchronization) with the final single-variable probe: DEPTH 4 -> 3.
// Measured depth curve (4: 88.2% DRAM, 5: 82.8%, 6: 81.4%) is monotone
// worse with depth — L1tex queue-position latency grows with pending
// stages — so the untested shallower point is the remaining candidate.
// 12KB smem, 1024 blocks x 64 thr, each thread owns 4 consecutive pixels.

#define OPACITY 0.8f
#define HW      262144              // 512*512
#define NLAYERS 128
#define DEPTH   3                   // stages (1 layer per stage)
#define TPB     64
#define LAYER_BYTES ((size_t)4 * HW * 4)   // bytes per layer (4 planes)

__device__ __forceinline__ void cp_async16(uint32_t smem_addr, const void* gptr)
{
    asm volatile("cp.async.cg.shared.global.L2::256B [%0], [%1], 16;\n"
                 :: "r"(smem_addr), "l"(gptr));
}
__device__ __forceinline__ void cp_commit()
{
    asm volatile("cp.async.commit_group;\n" ::: "memory");
}
__device__ __forceinline__ void cp_wait_oldest()
{
    asm volatile("cp.async.wait_group %0;\n" :: "n"(DEPTH - 1) : "memory");
}

__global__ __launch_bounds__(TPB)
void painting_kernel(const float* __restrict__ polys,
                     float* __restrict__ out)
{
    // [stage][channel][thread] float4 : 3*4*64*16B = 12KB
    __shared__ float4 sbuf[DEPTH][4][TPB];

    const int t = threadIdx.x;
    const int q = (blockIdx.x * TPB + t) * 4;   // first of this thread's 4 pixels

    const uint32_t smem0 = (uint32_t)__cvta_generic_to_shared(&sbuf[0][0][t]);
    // sbuf[slot][c][t] = smem0 + (slot*4 + c) * (TPB*16)

    // running source pointer: advances by one layer per issue; channels are
    // fixed +c*HW float offsets. Addressing independent of the layer index.
    const char* gptr = (const char*)(polys + q);

    auto issue_layer = [&](int slot) {
#pragma unroll
        for (int c = 0; c < 4; ++c) {
            cp_async16(smem0 + (uint32_t)(slot * 4 + c) * (TPB * 16),
                       gptr + (size_t)c * (HW * 4));
        }
        cp_commit();
        gptr += LAYER_BYTES;
    };

    // ---- prologue: fill the pipe ----
#pragma unroll
    for (int k = 0; k < DEPTH; ++k)
        issue_layer(k);

    float4 c0 = make_float4(1.f, 1.f, 1.f, 1.f);
    float4 c1 = c0, c2 = c0, c3 = c0;

    int slot = 0;
    for (int l = 0; l < NLAYERS; ++l) {
        cp_wait_oldest();   // this thread's oldest stage complete; it reads
                            // only its own cp.async results -> no syncs.

        float4 p0 = sbuf[slot][0][t];
        float4 p1 = sbuf[slot][1][t];
        float4 p2 = sbuf[slot][2][t];
        float4 p3 = sbuf[slot][3][t];

        float ax = p3.x * OPACITY;
        float ay = p3.y * OPACITY;
        float az = p3.z * OPACITY;
        float aw = p3.w * OPACITY;

        c0.x = fmaf(ax, p0.x - c0.x, c0.x);
        c0.y = fmaf(ay, p0.y - c0.y, c0.y);
        c0.z = fmaf(az, p0.z - c0.z, c0.z);
        c0.w = fmaf(aw, p0.w - c0.w, c0.w);

        c1.x = fmaf(ax, p1.x - c1.x, c1.x);
        c1.y = fmaf(ay, p1.y - c1.y, c1.y);
        c1.z = fmaf(az, p1.z - c1.z, c1.z);
        c1.w = fmaf(aw, p1.w - c1.w, c1.w);

        c2.x = fmaf(ax, p2.x - c2.x, c2.x);
        c2.y = fmaf(ay, p2.y - c2.y, c2.y);
        c2.z = fmaf(az, p2.z - c2.z, c2.z);
        c2.w = fmaf(aw, p2.w - c2.w, c2.w);

        c3.x = fmaf(ax, p3.x - c3.x, c3.x);
        c3.y = fmaf(ay, p3.y - c3.y, c3.y);
        c3.z = fmaf(az, p3.z - c3.z, c3.z);
        c3.w = fmaf(aw, p3.w - c3.w, c3.w);

        if (l + DEPTH < NLAYERS)
            issue_layer(slot);
        else
            cp_commit();    // empty group keeps wait_group count aligned

        slot = (slot == DEPTH - 1) ? 0 : slot + 1;
    }

    *(float4*)(out +          q) = c0;
    *(float4*)(out +     HW + q) = c1;
    *(float4*)(out + 2 * HW + q) = c2;
    *(float4*)(out + 3 * HW + q) = c3;
}

extern "C" void kernel_launch(void* const* d_in, const int* in_sizes, int n_in,
                              void* d_out, int out_size)
{
    const float* polys = (const float*)d_in[0];
    float* out = (float*)d_out;

    const int blocks = HW / 4 / TPB;   // 1024
    painting_kernel<<<blocks, TPB>>>(polys, out);
}